// round 15
// baseline (speedup 1.0000x reference)
#include <cuda_runtime.h>
#include <cstdint>

#define NB   32
#define NQ   300
#define NC   11
#define NT   3200
#define NP   (NB*NQ)        // 9600 predictions
#define PF   16             // floats/pred record: [0..10]=2-prob, [11]=area+eps, [12]=cx,[13]=cy,[14]=w/2,[15]=h/2
#define PPB  4              // preds per tile
#define NTILES (NP/PPB)     // 2400
#define GRD  148            // persistent: one block per SM
#define THR  800            // 25 warps; 800*4 = 3200 targets
#define EPSV 1e-6f

typedef unsigned long long ull;

// ---- packed f32x2 helpers (sm_100+; ptxas never auto-generates these) ----
#define F32X2_FMA(d,a,b,c) asm("fma.rn.f32x2 %0, %1, %2, %3;" : "=l"(d) : "l"(a), "l"(b), "l"(c))
#define F32X2_ADD(d,a,b)   asm("add.rn.f32x2 %0, %1, %2;"     : "=l"(d) : "l"(a), "l"(b))
#define F32X2_PACK(d,lo,hi)   asm("mov.b64 %0, {%1, %2};" : "=l"(d) : "f"(lo), "f"(hi))
#define F32X2_UNPACK(lo,hi,s) asm("mov.b64 {%0, %1}, %2;" : "=f"(lo), "=f"(hi) : "l"(s))

// ---- scratch (no allocations allowed) ----
__device__ float g_pred[NP * PF];

// ---------------- precompute: pred records ----------------
__global__ void precompute_kernel(const float* __restrict__ logits,
                                  const float* __restrict__ pboxes) {
    const int i = blockIdx.x * blockDim.x + threadIdx.x;
    if (i >= NP) return;
    const float* l = logits + i * NC;
    float v[NC];
    float m = -1e30f;
#pragma unroll
    for (int c = 0; c < NC; c++) { v[c] = l[c]; m = fmaxf(m, v[c]); }
    float s = 0.f;
#pragma unroll
    for (int c = 0; c < NC; c++) { v[c] = __expf(v[c] - m); s += v[c]; }
    float inv = __fdividef(1.f, s);
    float* o = g_pred + i * PF;
#pragma unroll
    for (int c = 0; c < NC; c++) o[c] = fmaf(-v[c], inv, 2.f);   // 2 - prob (giou const folded)
    const float4 bb = reinterpret_cast<const float4*>(pboxes)[i];
    o[11] = bb.z * bb.w + EPSV;                                  // area + eps
    o[12] = bb.x;        o[13] = bb.y;                           // (cx,cy) 8B-aligned pair
    o[14] = 0.5f * bb.z; o[15] = 0.5f * bb.w;                    // (w/2,h/2) 8B-aligned pair
}

// one output element (validated R9 math, x/y axes packed in f32x2):
//   C = (2 - prob) + 5*L1 - 2*(inter*d2 + d1^2)/(d1*d2)
__device__ __forceinline__ float cost_elem(
    float spval, ull pxy, ull pwh, float paeps,
    ull txy, ull twh, float ta, ull M1)
{
    ull dxy, dwh, swh;
    F32X2_FMA(dxy, txy, M1, pxy);       // (pcx-tcx, pcy-tcy)
    F32X2_FMA(dwh, twh, M1, pwh);       // (pw2-tw2, ph2-th2)
    F32X2_ADD(swh, pwh, twh);           // (sw, sh)
    float dx, dy, dw, dh;
    F32X2_UNPACK(dx, dy, dxy);
    F32X2_UNPACK(dw, dh, dwh);
    float mx = fmaxf(fabsf(dx), fabsf(dw));   // FMNMX with |src| modifiers
    float my = fmaxf(fabsf(dy), fabsf(dh));
    ull mxy;
    F32X2_PACK(mxy, mx, my);
    ull ixy, exy;
    F32X2_FMA(ixy, mxy, M1, swh);       // (sw-mx, sh-my)   intersection extents
    F32X2_ADD(exy, swh, mxy);           // (sw+mx, sh+my)   enclosing extents
    float ixr, iyr, ex, ey;
    F32X2_UNPACK(ixr, iyr, ixy);
    F32X2_UNPACK(ex,  ey,  exy);
    float ix = fmaxf(ixr, 0.f), iy = fmaxf(iyr, 0.f);
    float inter = ix * iy;
    float d1 = (paeps + ta) - inter;    // union + eps
    float d2 = fmaf(ex, ey, EPSV);      // area_c + eps
    float num = fmaf(inter, d2, d1 * d1);
    float den = d1 * d2;
    float q = __fdividef(num, den);
    float acc = fmaf(5.f,  fabsf(dx) + fabsf(dy), spval);   // FADD |src| mods
    acc       = fmaf(10.f, fabsf(dw) + fabsf(dh), acc);
    return fmaf(-2.f, q, acc);
}

// ---------------- persistent cost kernel (R14 structure) ----------------
__global__ __launch_bounds__(THR, 1) void cost_kernel(
    const int*   __restrict__ tlabels,
    const float* __restrict__ tboxes,
    float*       __restrict__ out)
{
    __shared__ float sp[2][PPB * PF];       // double-buffered pred tiles (512 B)
    const int tid = threadIdx.x;

    const ull M1 = 0xBF800000BF800000ull;   // packed (-1.0f, -1.0f)

    // ---- prologue: 4 consecutive targets per thread, packed in registers ----
    ull   tkxy[4], tkwh[4];
    float ta[4];
    int   lab[4];
    {
        const int t0 = tid * 4;
        const int4 lv = *reinterpret_cast<const int4*>(tlabels + t0);
        lab[0] = lv.x; lab[1] = lv.y; lab[2] = lv.z; lab[3] = lv.w;
#pragma unroll
        for (int j = 0; j < 4; j++) {
            const float4 bb = reinterpret_cast<const float4*>(tboxes)[t0 + j];
            F32X2_PACK(tkxy[j], bb.x, bb.y);
            float w2 = 0.5f * bb.z, h2 = 0.5f * bb.w;
            F32X2_PACK(tkwh[j], w2, h2);
            ta[j] = bb.z * bb.w;
        }
    }

    // stage first tile
    int tile = blockIdx.x;
    if (tid < PPB * PF)
        sp[0][tid] = g_pred[tile * (PPB * PF) + tid];
    __syncthreads();

    int nb = 0;
    for (; tile < NTILES; tile += GRD) {
        const int nxt = tile + GRD;
        if (nxt < NTILES && tid < PPB * PF)
            sp[nb ^ 1][tid] = g_pred[nxt * (PPB * PF) + tid];

        float* obase = out + (size_t)tile * (PPB * NT) + (size_t)tid * 4;
        const float* buf = sp[nb];

#pragma unroll
        for (int p = 0; p < PPB; p++) {
            const float* pp = buf + p * PF;                       // broadcast LDS
            const float paeps = pp[11];
            const ull pxy = *reinterpret_cast<const ull*>(pp + 12);   // LDS.64 packed (cx,cy)
            const ull pwh = *reinterpret_cast<const ull*>(pp + 14);   // LDS.64 packed (w2,h2)

            float4 r;
            r.x = cost_elem(pp[lab[0]], pxy, pwh, paeps, tkxy[0], tkwh[0], ta[0], M1);
            r.y = cost_elem(pp[lab[1]], pxy, pwh, paeps, tkxy[1], tkwh[1], ta[1], M1);
            r.z = cost_elem(pp[lab[2]], pxy, pwh, paeps, tkxy[2], tkwh[2], ta[2], M1);
            r.w = cost_elem(pp[lab[3]], pxy, pwh, paeps, tkxy[3], tkwh[3], ta[3], M1);

            *reinterpret_cast<float4*>(obase + (size_t)p * NT) = r;   // STG.128
        }

        __syncthreads();
        nb ^= 1;
    }
}

extern "C" void kernel_launch(void* const* d_in, const int* in_sizes, int n_in,
                              void* d_out, int out_size) {
    const float* logits  = (const float*)d_in[0];  // [B,Q,C]
    const float* pboxes  = (const float*)d_in[1];  // [B,Q,4]
    const int*   tlabels = (const int*)  d_in[2];  // [T]
    const float* tboxes  = (const float*)d_in[3];  // [T,4]
    float*       out     = (float*)d_out;          // [B,Q,T]

    precompute_kernel<<<NP / 64, 64>>>(logits, pboxes);
    cost_kernel<<<GRD, THR>>>(tlabels, tboxes, out);
}

// round 17
// speedup vs baseline: 1.1483x; 1.1483x over previous
#include <cuda_runtime.h>
#include <cstdint>

#define NB   32
#define NQ   300
#define NC   11
#define NT   3200
#define NP   (NB*NQ)        // 9600 predictions
#define PF   16             // floats/pred record: [0..10]=2-prob, 11=cx,12=cy,13=w/2,14=h/2,15=area+eps
#define PPB  4              // preds per tile
#define NTILES (NP/PPB)     // 2400
#define GRD  148            // persistent: one block per SM
#define THR  800            // 25 warps; 800*4 = 3200 targets
#define MAXT 17             // max tiles per block: ceil(2400/148)
#define EPSV 1e-6f

// one output element (validated R9/R14 math):
//   C = (2 - prob) + 5*L1 - 2*(inter*d2 + d1^2)/(d1*d2)
__device__ __forceinline__ float cost_elem(
    float spval,
    float pcx, float pcy, float pw2, float ph2, float paeps,
    float tcx, float tcy, float tw2, float th2, float ta)
{
    float adx = fabsf(pcx - tcx), ady = fabsf(pcy - tcy);
    float adw = fabsf(pw2 - tw2), adh = fabsf(ph2 - th2);
    float l1a = adx + ady;
    float l1b = adw + adh;
    float sw = pw2 + tw2,        sh = ph2 + th2;
    float mx = fmaxf(adx, adw),  my = fmaxf(ady, adh);
    float ixr = sw - mx,         iyr = sh - my;
    float ex  = sw + mx,         ey  = sh + my;
    float ix = fmaxf(ixr, 0.f),  iy = fmaxf(iyr, 0.f);
    float inter = ix * iy;
    float d1 = (paeps + ta) - inter;
    float d2 = fmaf(ex, ey, EPSV);
    float num = fmaf(inter, d2, d1 * d1);
    float den = d1 * d2;
    float acc = fmaf(5.f, l1a, spval);
    acc = fmaf(10.f, l1b, acc);
    float q = __fdividef(num, den);
    return fmaf(-2.f, q, acc);
}

// ---------------- single persistent kernel ----------------
__global__ __launch_bounds__(THR, 1) void cost_kernel(
    const float* __restrict__ logits,
    const float* __restrict__ pboxes,
    const int*   __restrict__ tlabels,
    const float* __restrict__ tboxes,
    float*       __restrict__ out)
{
    __shared__ float sp[MAXT * PPB * PF];   // all of this block's pred records (4.25 KB)
    const int tid = threadIdx.x;
    const int bid = blockIdx.x;

    // number of tiles this block owns: tiles bid, bid+GRD, ...
    const int L = (bid < NTILES - (MAXT - 1) * GRD) ? MAXT : (MAXT - 1);

    // ---- prologue A: softmax + box record for this block's own preds ----
    // local pred index lp -> global pred (bid + (lp/PPB)*GRD)*PPB + lp%PPB
    if (tid < L * PPB) {
        const int lt = tid >> 2;            // local tile
        const int pl = tid & 3;             // pred within tile
        const int n  = (bid + lt * GRD) * PPB + pl;
        const float* l = logits + n * NC;
        float v[NC];
        float m = -1e30f;
#pragma unroll
        for (int c = 0; c < NC; c++) { v[c] = l[c]; m = fmaxf(m, v[c]); }
        float s = 0.f;
#pragma unroll
        for (int c = 0; c < NC; c++) { v[c] = __expf(v[c] - m); s += v[c]; }
        const float inv = __fdividef(1.f, s);
        float* o = sp + tid * PF;
#pragma unroll
        for (int c = 0; c < NC; c++) o[c] = fmaf(-v[c], inv, 2.f);   // 2 - prob
        const float4 bb = reinterpret_cast<const float4*>(pboxes)[n];
        o[11] = bb.x; o[12] = bb.y;
        o[13] = 0.5f * bb.z; o[14] = 0.5f * bb.w;
        o[15] = bb.z * bb.w + EPSV;                                  // area + eps
    }

    // ---- prologue B: 4 consecutive targets per thread, resident in registers ----
    float tcx[4], tcy[4], tw2[4], th2[4], ta[4];
    int   lab[4];
    {
        const int t0 = tid * 4;
        const int4 lv = *reinterpret_cast<const int4*>(tlabels + t0);
        lab[0] = lv.x; lab[1] = lv.y; lab[2] = lv.z; lab[3] = lv.w;
#pragma unroll
        for (int j = 0; j < 4; j++) {
            const float4 bb = reinterpret_cast<const float4*>(tboxes)[t0 + j];
            tcx[j] = bb.x;         tcy[j] = bb.y;
            tw2[j] = 0.5f * bb.z;  th2[j] = 0.5f * bb.w;
            ta[j]  = bb.z * bb.w;
        }
    }

    __syncthreads();     // the only barrier: records fully staged, read-only after

    // ---- main loop: no syncs, incremental pointers ----
    float* obase = out + (size_t)bid * (PPB * NT) + (size_t)tid * 4;
    const float* buf = sp;

    for (int k = 0; k < L; k++) {
#pragma unroll 2
        for (int p = 0; p < PPB; p++) {
            const float* pp = buf + p * PF;                 // broadcast LDS
            const float pcx = pp[11], pcy = pp[12], pw2 = pp[13], ph2 = pp[14];
            const float paeps = pp[15];

            float4 r;
            r.x = cost_elem(pp[lab[0]], pcx, pcy, pw2, ph2, paeps,
                            tcx[0], tcy[0], tw2[0], th2[0], ta[0]);
            r.y = cost_elem(pp[lab[1]], pcx, pcy, pw2, ph2, paeps,
                            tcx[1], tcy[1], tw2[1], th2[1], ta[1]);
            r.z = cost_elem(pp[lab[2]], pcx, pcy, pw2, ph2, paeps,
                            tcx[2], tcy[2], tw2[2], th2[2], ta[2]);
            r.w = cost_elem(pp[lab[3]], pcx, pcy, pw2, ph2, paeps,
                            tcx[3], tcy[3], tw2[3], th2[3], ta[3]);

            *reinterpret_cast<float4*>(obase + (size_t)p * NT) = r;   // STG.128
        }
        buf   += PPB * PF;                       // next local tile's records
        obase += (size_t)GRD * (PPB * NT);       // next owned tile's output rows
    }
}

extern "C" void kernel_launch(void* const* d_in, const int* in_sizes, int n_in,
                              void* d_out, int out_size) {
    const float* logits  = (const float*)d_in[0];  // [B,Q,C]
    const float* pboxes  = (const float*)d_in[1];  // [B,Q,4]
    const int*   tlabels = (const int*)  d_in[2];  // [T]
    const float* tboxes  = (const float*)d_in[3];  // [T,4]
    float*       out     = (float*)d_out;          // [B,Q,T]

    cost_kernel<<<GRD, THR>>>(logits, pboxes, tlabels, tboxes, out);
}